// round 9
// baseline (speedup 1.0000x reference)
#include <cuda_runtime.h>
#include <cstdint>

static constexpr int HID = 2048;
static constexpr int HV4 = HID / 4;          // 512 float4 per row
static constexpr int NTHREADS = 512;
static constexpr int NWARP = NTHREADS / 32;  // 16
static constexpr int RPAD = NWARP + 1;       // 17: conflict-free stride

__device__ __forceinline__ float tanh_fast(float x) {
    float r;
    asm("tanh.approx.f32 %0, %1;" : "=f"(r) : "f"(x));
    return r;
}

__global__ __launch_bounds__(NTHREADS, 3)
void altup_kernel(const float* __restrict__ hs,    // [4, T, H]
                  const float* __restrict__ act,   // [T, H]
                  const float* __restrict__ rns,   // [H]
                  const float* __restrict__ rw,    // [H, 4]
                  const float* __restrict__ pw,    // [4, 16]
                  const float* __restrict__ cw,    // [4, 4]
                  const float* __restrict__ cosc,  // [H]
                  float* __restrict__ out,         // [4, T, H]
                  int n_tokens)
{
    __shared__ float4 wsm[4][NTHREADS];      // folded router weights (32 KB)
    __shared__ float red[2][10][RPAD];

    const int tid  = threadIdx.x;
    const int lane = tid & 31;
    const int warp = tid >> 5;

    // ---- prologue: fold rns into rw, park in SMEM ----
    {
        const float4 rsc = ((const float4*)rns)[tid];
        const float4* rw4 = (const float4*)rw;
        float4 w0 = rw4[4 * tid + 0];
        float4 w1 = rw4[4 * tid + 1];
        float4 w2 = rw4[4 * tid + 2];
        float4 w3 = rw4[4 * tid + 3];
        w0.x *= rsc.x; w0.y *= rsc.x; w0.z *= rsc.x; w0.w *= rsc.x;
        w1.x *= rsc.y; w1.y *= rsc.y; w1.z *= rsc.y; w1.w *= rsc.y;
        w2.x *= rsc.z; w2.y *= rsc.z; w2.z *= rsc.z; w2.w *= rsc.z;
        w3.x *= rsc.w; w3.y *= rsc.w; w3.z *= rsc.w; w3.w *= rsc.w;
        wsm[0][tid] = w0; wsm[1][tid] = w1; wsm[2][tid] = w2; wsm[3][tid] = w3;
    }
    const float4 cs = ((const float4*)cosc)[tid];

    // per-lane coefficient column: lanes 0-15 -> pw[:,lane], 16-19 -> cw[:,lane-16]
    float pv0 = 0.f, pv1 = 0.f, pv2 = 0.f, pv3 = 0.f;
    if (lane < 16) {
        pv0 = pw[lane]; pv1 = pw[16 + lane]; pv2 = pw[32 + lane]; pv3 = pw[48 + lane];
    } else if (lane < 20) {
        const int m = lane - 16;
        pv0 = cw[m]; pv1 = cw[4 + m]; pv2 = cw[8 + m]; pv3 = cw[12 + m];
    }
    const int mrow = lane >> 2;
    const int ncol = lane & 3;
    const float diag = (lane < 16 && mrow == ncol) ? 1.f : 0.f;

    const size_t plane = (size_t)n_tokens * HV4;
    const float4* hsv  = (const float4*)hs;
    const float4* actv = (const float4*)act;
    float4* outv = (float4*)out;

    __syncthreads();   // wsm visible

    int par = 0;
    for (int t = blockIdx.x; t < n_tokens; t += gridDim.x) {
        const size_t tb = (size_t)t * HV4 + tid;

        // all 5 loads at loop top — hiding comes from the 2 other CTAs/SM
        const float4 x0 = __ldcs(hsv + tb);
        const float4 a  = __ldcs(actv + tb);
        const float4 x1 = __ldcs(hsv + plane + tb);
        const float4 x2 = __ldcs(hsv + 2 * plane + tb);
        const float4 x3 = __ldcs(hsv + 3 * plane + tb);

        // ---- 10 per-thread partials (weights from SMEM) ----
        const float4 w0 = wsm[0][tid];
        const float4 w1 = wsm[1][tid];
        const float4 w2 = wsm[2][tid];
        const float4 w3 = wsm[3][tid];
        float p[10];
        p[0] = x0.x*x0.x + x0.y*x0.y + x0.z*x0.z + x0.w*x0.w;
        p[1] = a.x*a.x + a.y*a.y + a.z*a.z + a.w*a.w;
        p[2] = x0.x*w0.x + x0.y*w1.x + x0.z*w2.x + x0.w*w3.x;
        p[3] = x0.x*w0.y + x0.y*w1.y + x0.z*w2.y + x0.w*w3.y;
        p[4] = x0.x*w0.z + x0.y*w1.z + x0.z*w2.z + x0.w*w3.z;
        p[5] = x0.x*w0.w + x0.y*w1.w + x0.z*w2.w + x0.w*w3.w;
        p[6] = a.x*w0.x + a.y*w1.x + a.z*w2.x + a.w*w3.x;
        p[7] = a.x*w0.y + a.y*w1.y + a.z*w2.y + a.w*w3.y;
        p[8] = a.x*w0.z + a.y*w1.z + a.z*w2.z + a.w*w3.z;
        p[9] = a.x*w0.w + a.y*w1.w + a.z*w2.w + a.w*w3.w;

        // ---- packed reduction: 10 + 20 shfls ----
        #pragma unroll
        for (int i = 0; i < 10; i++)
            p[i] += __shfl_xor_sync(0xffffffffu, p[i], 16);
        float q[5];
        #pragma unroll
        for (int j = 0; j < 5; j++)
            q[j] = (lane < 16) ? p[j] : p[j + 5];
        #pragma unroll
        for (int off = 8; off > 0; off >>= 1) {
            #pragma unroll
            for (int j = 0; j < 5; j++)
                q[j] += __shfl_xor_sync(0xffffffffu, q[j], off);
        }
        if (lane == 0) {
            #pragma unroll
            for (int j = 0; j < 5; j++) red[par][j][warp] = q[j];
        } else if (lane == 16) {
            #pragma unroll
            for (int j = 0; j < 5; j++) red[par][5 + j][warp] = q[j];
        }

        __syncthreads();   // the ONLY barrier per token

        // ---- redundant per-warp tail ----
        float v = 0.f;
        if (lane < 10) {
            #pragma unroll
            for (int w = 0; w < NWARP; w++) v += red[par][lane][w];
        }
        const float ssq0 = __shfl_sync(0xffffffffu, v, 0);
        const float ssq1 = __shfl_sync(0xffffffffu, v, 1);
        const float invH = 1.0f / (float)HID;
        const float ih = rsqrtf(ssq0 * invH + 1e-6f) * invH;
        const float ia = rsqrtf(ssq1 * invH + 1e-6f) * invH;

        const float argp = __shfl_sync(0xffffffffu, v, 2 + (lane & 3));
        const float argc = __shfl_sync(0xffffffffu, v, 6 + (lane & 3));
        const float tv = tanh_fast((lane < 4) ? argp * ih : argc * ia);

        const int base = (lane < 16) ? 0 : 4;
        const float m0 = __shfl_sync(0xffffffffu, tv, base + 0);
        const float m1 = __shfl_sync(0xffffffffu, tv, base + 1);
        const float m2 = __shfl_sync(0xffffffffu, tv, base + 2);
        const float m3 = __shfl_sync(0xffffffffu, tv, base + 3);
        // lanes 0-15: raw[m,n]; lanes 16-19: c_m
        const float val = ((lane < 16) ? 0.f : 1.f)
                        + m0 * pv0 + m1 * pv1 + m2 * pv2 + m3 * pv3;

        // ---- fuse: A[m,n] = (δ+raw)[m,n] - c_m*(δ+raw)[0,n] ----
        const float cm_row = __shfl_sync(0xffffffffu, val, 16 + mrow);
        const float p0n    = __shfl_sync(0xffffffffu, val, ncol)
                           + ((ncol == 0) ? 1.f : 0.f);
        float coef = val;
        if (lane < 16) coef = val + diag - cm_row * p0n;

        // ---- phase 2: 4 independent fused streams ----
        #pragma unroll
        for (int m = 0; m < 4; m++) {
            const float A0 = __shfl_sync(0xffffffffu, coef, m * 4 + 0);
            const float A1 = __shfl_sync(0xffffffffu, coef, m * 4 + 1);
            const float A2 = __shfl_sync(0xffffffffu, coef, m * 4 + 2);
            const float A3 = __shfl_sync(0xffffffffu, coef, m * 4 + 3);
            const float cm = __shfl_sync(0xffffffffu, coef, 16 + m);
            float4 o;
            o.x = (A0*x0.x + A1*x1.x + A2*x2.x + A3*x3.x + cm*a.x) * cs.x;
            o.y = (A0*x0.y + A1*x1.y + A2*x2.y + A3*x3.y + cm*a.y) * cs.y;
            o.z = (A0*x0.z + A1*x1.z + A2*x2.z + A3*x3.z + cm*a.z) * cs.z;
            o.w = (A0*x0.w + A1*x1.w + A2*x2.w + A3*x3.w + cm*a.w) * cs.w;
            __stcs(&outv[(size_t)m * plane + tb], o);
        }
        par ^= 1;
    }
}

extern "C" void kernel_launch(void* const* d_in, const int* in_sizes, int n_in,
                              void* d_out, int out_size) {
    const float* hs   = (const float*)d_in[0];
    const float* act  = (const float*)d_in[1];
    const float* rns  = (const float*)d_in[2];
    const float* rw   = (const float*)d_in[3];
    const float* pw   = (const float*)d_in[4];
    const float* cw   = (const float*)d_in[5];
    const float* cosc = (const float*)d_in[6];
    float* out = (float*)d_out;

    const int n_tokens = in_sizes[1] / HID;
    const int grid = 456;   // 3 CTAs/SM on 152 SMs, single wave
    altup_kernel<<<grid, NTHREADS>>>(hs, act, rns, rw, pw, cw, cosc, out, n_tokens);
}

// round 10
// speedup vs baseline: 1.1262x; 1.1262x over previous
#include <cuda_runtime.h>
#include <cstdint>

static constexpr int HID = 2048;
static constexpr int HV4 = HID / 4;          // 512 float4 per row
static constexpr int NTHREADS = 512;
static constexpr int NWARP = NTHREADS / 32;  // 16
static constexpr int RPAD = NWARP + 1;       // 17: conflict-free stride

__device__ __forceinline__ float tanh_fast(float x) {
    float r;
    asm("tanh.approx.f32 %0, %1;" : "=f"(r) : "f"(x));
    return r;
}

__global__ __launch_bounds__(NTHREADS, 2)
void altup_kernel(const float* __restrict__ hs,    // [4, T, H]
                  const float* __restrict__ act,   // [T, H]
                  const float* __restrict__ rns,   // [H]
                  const float* __restrict__ rw,    // [H, 4]
                  const float* __restrict__ pw,    // [4, 16]
                  const float* __restrict__ cw,    // [4, 4]
                  const float* __restrict__ cosc,  // [H]
                  float* __restrict__ out,         // [4, T, H]
                  int n_tokens)
{
    __shared__ float4 wsm[4][NTHREADS];      // folded router weights (32 KB)
    __shared__ float red[2][10][RPAD];

    const int tid  = threadIdx.x;
    const int lane = tid & 31;
    const int warp = tid >> 5;

    // ---- prologue: fold rns into rw, park in SMEM ----
    {
        const float4 rsc = ((const float4*)rns)[tid];
        const float4* rw4 = (const float4*)rw;
        float4 w0 = rw4[4 * tid + 0];
        float4 w1 = rw4[4 * tid + 1];
        float4 w2 = rw4[4 * tid + 2];
        float4 w3 = rw4[4 * tid + 3];
        w0.x *= rsc.x; w0.y *= rsc.x; w0.z *= rsc.x; w0.w *= rsc.x;
        w1.x *= rsc.y; w1.y *= rsc.y; w1.z *= rsc.y; w1.w *= rsc.y;
        w2.x *= rsc.z; w2.y *= rsc.z; w2.z *= rsc.z; w2.w *= rsc.z;
        w3.x *= rsc.w; w3.y *= rsc.w; w3.z *= rsc.w; w3.w *= rsc.w;
        wsm[0][tid] = w0; wsm[1][tid] = w1; wsm[2][tid] = w2; wsm[3][tid] = w3;
    }
    const float4 cs = ((const float4*)cosc)[tid];

    // per-lane coefficient column: lanes 0-15 -> pw[:,lane], 16-19 -> cw[:,lane-16]
    float pv0 = 0.f, pv1 = 0.f, pv2 = 0.f, pv3 = 0.f;
    if (lane < 16) {
        pv0 = pw[lane]; pv1 = pw[16 + lane]; pv2 = pw[32 + lane]; pv3 = pw[48 + lane];
    } else if (lane < 20) {
        const int m = lane - 16;
        pv0 = cw[m]; pv1 = cw[4 + m]; pv2 = cw[8 + m]; pv3 = cw[12 + m];
    }

    const size_t plane  = (size_t)n_tokens * HV4;
    const size_t stride = (size_t)gridDim.x * HV4;   // loop stride in float4
    const float4* hsv  = (const float4*)hs;
    const float4* actv = (const float4*)act;
    float4* outv = (float4*)out;

    // ---- prefetch first token (all 5 rows) ----
    const int t0 = blockIdx.x;
    float4 n0, n1, n2, n3, n4;
    n0 = n1 = n2 = n3 = n4 = make_float4(0.f, 0.f, 0.f, 0.f);
    size_t tb = (size_t)t0 * HV4 + tid;              // running base index
    if (t0 < n_tokens) {
        n0 = __ldcs(hsv + tb);
        n1 = __ldcs(hsv + plane + tb);
        n2 = __ldcs(hsv + 2 * plane + tb);
        n3 = __ldcs(hsv + 3 * plane + tb);
        n4 = __ldcs(actv + tb);
    }
    __syncthreads();   // wsm visible

    int par = 0;
    for (int t = t0; t < n_tokens; t += gridDim.x, tb += stride) {
        const float4 x0 = n0, x1 = n1, x2 = n2, x3 = n3, a = n4;

        // ---- 10 per-thread partials (weights from SMEM) ----
        const float4 w0 = wsm[0][tid];
        const float4 w1 = wsm[1][tid];
        const float4 w2 = wsm[2][tid];
        const float4 w3 = wsm[3][tid];
        float p[10];
        p[0] = x0.x*x0.x + x0.y*x0.y + x0.z*x0.z + x0.w*x0.w;
        p[1] = a.x*a.x + a.y*a.y + a.z*a.z + a.w*a.w;
        p[2] = x0.x*w0.x + x0.y*w1.x + x0.z*w2.x + x0.w*w3.x;
        p[3] = x0.x*w0.y + x0.y*w1.y + x0.z*w2.y + x0.w*w3.y;
        p[4] = x0.x*w0.z + x0.y*w1.z + x0.z*w2.z + x0.w*w3.z;
        p[5] = x0.x*w0.w + x0.y*w1.w + x0.z*w2.w + x0.w*w3.w;
        p[6] = a.x*w0.x + a.y*w1.x + a.z*w2.x + a.w*w3.x;
        p[7] = a.x*w0.y + a.y*w1.y + a.z*w2.y + a.w*w3.y;
        p[8] = a.x*w0.z + a.y*w1.z + a.z*w2.z + a.w*w3.z;
        p[9] = a.x*w0.w + a.y*w1.w + a.z*w2.w + a.w*w3.w;

        #pragma unroll
        for (int i = 0; i < 10; i++) {
            #pragma unroll
            for (int off = 16; off > 0; off >>= 1)
                p[i] += __shfl_xor_sync(0xffffffffu, p[i], off);
        }
        if (lane < 10) red[par][lane][warp] = p[lane];

        // ---- prefetch ALL of next token (hidden under barrier+tail+phase2) ----
        if (t + gridDim.x < n_tokens) {
            const size_t tnb = tb + stride;
            n0 = __ldcs(hsv + tnb);
            n1 = __ldcs(hsv + plane + tnb);
            n2 = __ldcs(hsv + 2 * plane + tnb);
            n3 = __ldcs(hsv + 3 * plane + tnb);
            n4 = __ldcs(actv + tnb);
        }

        __syncthreads();   // the ONLY barrier per token

        // ---- redundant per-warp tail ----
        float v = 0.f;
        if (lane < 10) {
            #pragma unroll
            for (int w = 0; w < NWARP; w++) v += red[par][lane][w];
        }
        const float ssq0 = __shfl_sync(0xffffffffu, v, 0);
        const float ssq1 = __shfl_sync(0xffffffffu, v, 1);
        const float invH = 1.0f / (float)HID;
        const float ih = rsqrtf(ssq0 * invH + 1e-6f) * invH;
        const float ia = rsqrtf(ssq1 * invH + 1e-6f) * invH;

        const float argp = __shfl_sync(0xffffffffu, v, 2 + (lane & 3));
        const float argc = __shfl_sync(0xffffffffu, v, 6 + (lane & 3));
        const float tv = tanh_fast((lane < 4) ? argp * ih : argc * ia);

        float mp0 = __shfl_sync(0xffffffffu, tv, 0);
        float mp1 = __shfl_sync(0xffffffffu, tv, 1);
        float mp2 = __shfl_sync(0xffffffffu, tv, 2);
        float mp3 = __shfl_sync(0xffffffffu, tv, 3);
        float mc0 = __shfl_sync(0xffffffffu, tv, 4);
        float mc1 = __shfl_sync(0xffffffffu, tv, 5);
        float mc2 = __shfl_sync(0xffffffffu, tv, 6);
        float mc3 = __shfl_sync(0xffffffffu, tv, 7);
        const float m0 = (lane < 16) ? mp0 : mc0;
        const float m1 = (lane < 16) ? mp1 : mc1;
        const float m2 = (lane < 16) ? mp2 : mc2;
        const float m3 = (lane < 16) ? mp3 : mc3;
        const float val = ((lane < 16) ? 0.f : 1.f)
                        + m0 * pv0 + m1 * pv1 + m2 * pv2 + m3 * pv3;

        const float r00 = __shfl_sync(0xffffffffu, val, 0);
        const float r01 = __shfl_sync(0xffffffffu, val, 1);
        const float r02 = __shfl_sync(0xffffffffu, val, 2);
        const float r03 = __shfl_sync(0xffffffffu, val, 3);
        const float c0  = __shfl_sync(0xffffffffu, val, 16);

        // ---- phase 2: mix, innovate, correct, scale, store ----
        float4 p0;
        p0.x = x0.x + r00*x0.x + r01*x1.x + r02*x2.x + r03*x3.x;
        p0.y = x0.y + r00*x0.y + r01*x1.y + r02*x2.y + r03*x3.y;
        p0.z = x0.z + r00*x0.z + r01*x1.z + r02*x2.z + r03*x3.z;
        p0.w = x0.w + r00*x0.w + r01*x1.w + r02*x2.w + r03*x3.w;
        float4 inn;
        inn.x = a.x - p0.x; inn.y = a.y - p0.y; inn.z = a.z - p0.z; inn.w = a.w - p0.w;

        {
            float4 o;
            o.x = (p0.x + c0 * inn.x) * cs.x;
            o.y = (p0.y + c0 * inn.y) * cs.y;
            o.z = (p0.z + c0 * inn.z) * cs.z;
            o.w = (p0.w + c0 * inn.w) * cs.w;
            __stcs(&outv[tb], o);
        }
        #pragma unroll
        for (int m = 1; m < 4; m++) {
            const float rm0 = __shfl_sync(0xffffffffu, val, m * 4 + 0);
            const float rm1 = __shfl_sync(0xffffffffu, val, m * 4 + 1);
            const float rm2 = __shfl_sync(0xffffffffu, val, m * 4 + 2);
            const float rm3 = __shfl_sync(0xffffffffu, val, m * 4 + 3);
            const float cm  = __shfl_sync(0xffffffffu, val, 16 + m);
            const float4 xm = (m == 1) ? x1 : ((m == 2) ? x2 : x3);
            float4 pm, o;
            pm.x = xm.x + rm0*x0.x + rm1*x1.x + rm2*x2.x + rm3*x3.x;
            pm.y = xm.y + rm0*x0.y + rm1*x1.y + rm2*x2.y + rm3*x3.y;
            pm.z = xm.z + rm0*x0.z + rm1*x1.z + rm2*x2.z + rm3*x3.z;
            pm.w = xm.w + rm0*x0.w + rm1*x1.w + rm2*x2.w + rm3*x3.w;
            o.x = (pm.x + cm * inn.x) * cs.x;
            o.y = (pm.y + cm * inn.y) * cs.y;
            o.z = (pm.z + cm * inn.z) * cs.z;
            o.w = (pm.w + cm * inn.w) * cs.w;
            __stcs(&outv[m * plane + tb], o);
        }
        par ^= 1;
    }
}

extern "C" void kernel_launch(void* const* d_in, const int* in_sizes, int n_in,
                              void* d_out, int out_size) {
    const float* hs   = (const float*)d_in[0];
    const float* act  = (const float*)d_in[1];
    const float* rns  = (const float*)d_in[2];
    const float* rw   = (const float*)d_in[3];
    const float* pw   = (const float*)d_in[4];
    const float* cw   = (const float*)d_in[5];
    const float* cosc = (const float*)d_in[6];
    float* out = (float*)d_out;

    const int n_tokens = in_sizes[1] / HID;
    const int grid = 304;   // 2 CTAs/SM on 152 SMs, single wave
    altup_kernel<<<grid, NTHREADS>>>(hs, act, rns, rw, pw, cw, cosc, out, n_tokens);
}